// round 6
// baseline (speedup 1.0000x reference)
#include <cuda_runtime.h>
#include <cuda_fp16.h>
#include <cstdint>

#define NB 2
#define NC 128
#define NN 4096      // H*W
#define NHD 8        // heads
#define DH 16        // head dim
#define NG 8         // groupnorm groups
#define GN_EPS 1e-5f
#define CSCALE 0.36067376022224085f   // 0.25 * log2(e)

// ======================= PTX helpers (baseline sm_80+ features only) =======
__device__ __forceinline__ uint32_t smem_u32(const void* p) {
    uint32_t a;
    asm("{ .reg .u64 t; cvta.to.shared.u64 t, %1; cvt.u32.u64 %0, t; }" : "=r"(a) : "l"(p));
    return a;
}
__device__ __forceinline__ void ldsm_x4(uint32_t* r, uint32_t a) {
    asm volatile("ldmatrix.sync.aligned.m8n8.x4.shared.b16 {%0,%1,%2,%3}, [%4];"
        : "=r"(r[0]), "=r"(r[1]), "=r"(r[2]), "=r"(r[3]) : "r"(a));
}
__device__ __forceinline__ void ldsm_x2t(uint32_t* r, uint32_t a) {
    asm volatile("ldmatrix.sync.aligned.m8n8.x2.trans.shared.b16 {%0,%1}, [%2];"
        : "=r"(r[0]), "=r"(r[1]) : "r"(a));
}
__device__ __forceinline__ void mma_fp16(float* d, const uint32_t* a,
                                         const uint32_t* b, const float* c) {
    asm volatile("mma.sync.aligned.m16n8k16.row.col.f32.f16.f16.f32 "
        "{%0,%1,%2,%3},{%4,%5,%6,%7},{%8,%9},{%10,%11,%12,%13};"
        : "=f"(d[0]), "=f"(d[1]), "=f"(d[2]), "=f"(d[3])
        : "r"(a[0]), "r"(a[1]), "r"(a[2]), "r"(a[3]), "r"(b[0]), "r"(b[1]),
          "f"(c[0]), "f"(c[1]), "f"(c[2]), "f"(c[3]));
}
__device__ __forceinline__ uint32_t exp2_pack(float lo, float hi) {
    uint32_t h;
    asm("cvt.rn.f16x2.f32 %0, %1, %2;" : "=r"(h) : "f"(hi), "f"(lo));
    asm("ex2.approx.f16x2 %0, %1;" : "=r"(h) : "r"(h));
    return h;
}
__device__ __forceinline__ uint32_t hadd2u(uint32_t a, uint32_t b) {
    uint32_t d; asm("add.rn.f16x2 %0, %1, %2;" : "=r"(d) : "r"(a), "r"(b)); return d;
}
__device__ __forceinline__ uint32_t f2h2(float lo, float hi) {
    __half2 h = __floats2half2_rn(lo, hi);
    return *reinterpret_cast<uint32_t*>(&h);
}

// ======================= scratch =============================================
__device__ __half g_q  [NB*NHD*NN*DH];   // [b,h,n,d], pre-scaled by CSCALE
__device__ __half g_k  [NB*NHD*NN*DH];   // [b,h,n,d]
__device__ __half g_v  [NB*NHD*NN*DH];   // [b,h,n,d]
__device__ __half g_aoh[NB*NN*NC];       // attention out fp16, [b,n,c]
__device__ float  g_proj[NB*NC*NN];      // out-proj fp32, channel-major [b,c,n]
__device__ float2 g_part[NB*NG*64];      // GN partial (sum, sumsq) per token-chunk

// ======================= Kernel A: fused QKV projection on HMMA =============
// grid NB*64: 64 tokens per CTA; q/k/v looped inside (x converted ONCE).
__global__ __launch_bounds__(128) void qkv_mma_kernel(
    const float* __restrict__ x,
    const float* __restrict__ Wq, const float* __restrict__ bq,
    const float* __restrict__ Wk, const float* __restrict__ bk,
    const float* __restrict__ Wv, const float* __restrict__ bv)
{
    __shared__ __align__(16) __half xs[64*136];
    __shared__ __align__(16) __half ws[128*72];
    __shared__ float bs[128];

    const int bi = blockIdx.x >> 6;
    const int n0 = (blockIdx.x & 63) * 64;
    const int tid = threadIdx.x, lane = tid & 31, wid = tid >> 5;

    {   // x tile [c=128][n=64] -> xs[n][c] fp16
        const int row = tid & 63, ch = (tid >> 6) * 64;
        const float* xp = x + (size_t)(bi*NC + ch)*NN + n0 + row;
        #pragma unroll 8
        for (int cc = 0; cc < 64; cc += 2) {
            float a = xp[(size_t)cc*NN];
            float b = xp[(size_t)(cc+1)*NN];
            *(uint32_t*)(xs + row*136 + ch + cc) = f2h2(a, b);
        }
    }
    __syncthreads();

    // A fragments for all 8 k-steps (shared by q/k/v)
    uint32_t qa[8][4];
    {
        uint32_t base = smem_u32(xs) +
            ((uint32_t)(wid*16 + (lane & 15))*136 + ((lane >> 4) & 1)*8)*2;
        #pragma unroll
        for (int k = 0; k < 8; ++k) ldsm_x4(qa[k], base + (uint32_t)k*32);
    }

    const float* Wm[3] = {Wq, Wk, Wv};
    const float* bm[3] = {bq, bk, bv};
    __half*      om[3] = {g_q, g_k, g_v};

    for (int m = 0; m < 3; ++m) {
        const float* __restrict__ W = Wm[m];
        bs[tid] = bm[m][tid];

        float of[16][4];
        #pragma unroll
        for (int t = 0; t < 16; ++t)
            #pragma unroll
            for (int j = 0; j < 4; ++j) of[t][j] = 0.f;

        for (int ph = 0; ph < 2; ++ph) {
            __syncthreads();
            for (int idx = tid; idx < 128*32; idx += 128) {
                int d = idx >> 5, cp = idx & 31;
                float2 wv = *(const float2*)(W + (size_t)d*NC + ph*64 + cp*2);
                *(uint32_t*)(ws + d*72 + cp*2) = f2h2(wv.x, wv.y);
            }
            __syncthreads();
            #pragma unroll
            for (int kk = 0; kk < 4; ++kk) {
                const int k = ph*4 + kk;
                uint32_t bbase = smem_u32(ws) +
                    ((uint32_t)(((lane >> 4) & 1)*8 + (lane & 7))*72)*2 +
                    (uint32_t)kk*32 + ((lane >> 3) & 1)*16;
                #pragma unroll
                for (int g = 0; g < 8; ++g) {
                    uint32_t bb[4];
                    ldsm_x4(bb, bbase + (uint32_t)g*16*72*2);
                    mma_fp16(of[2*g],   qa[k], bb,     of[2*g]);
                    mma_fp16(of[2*g+1], qa[k], bb + 2, of[2*g+1]);
                }
            }
        }

        const float s = (m == 0) ? CSCALE : 1.f;
        __half* __restrict__ outp = om[m];
        const int r = wid*16 + (lane >> 2);
        #pragma unroll
        for (int nt = 0; nt < 16; ++nt) {
            int c0 = nt*8 + (lane & 3)*2;
            int h = c0 >> 4, d = c0 & 15;
            __half* dst = outp + ((size_t)((bi*NHD + h)*NN) + n0 + r)*DH + d;
            *(uint32_t*)dst          = f2h2((of[nt][0]+bs[c0])*s, (of[nt][1]+bs[c0+1])*s);
            *(uint32_t*)(dst + 8*DH) = f2h2((of[nt][2]+bs[c0])*s, (of[nt][3]+bs[c0+1])*s);
        }
        __syncthreads();   // bs / ws reuse
    }
}

// ======================= Kernel B: HMMA flash attention (double-buffered) ===
__global__ __launch_bounds__(128) void attn_mma_kernel()
{
    __shared__ __align__(16) __half qs[128*24];
    __shared__ __align__(16) __half ks[2*128*24];
    __shared__ __align__(16) __half vs[2*128*24];

    const int bh = blockIdx.x;
    const int n0 = blockIdx.y * 128;
    const int tid = threadIdx.x, lane = tid & 31, wid = tid >> 5;

    const __half* __restrict__ qg = g_q + (size_t)bh*NN*DH;
    const __half* __restrict__ kg = g_k + (size_t)bh*NN*DH;
    const __half* __restrict__ vg = g_v + (size_t)bh*NN*DH;

    {   // Q tile: one row per thread
        const uint4* q4 = (const uint4*)(qg + (size_t)(n0 + tid)*DH);
        *(uint4*)(qs + tid*24)     = q4[0];
        *(uint4*)(qs + tid*24 + 8) = q4[1];
    }
    uint4 pk0, pk1, pv0, pv1;
    {
        const uint4* kp = (const uint4*)(kg + (size_t)tid*DH);
        pk0 = kp[0]; pk1 = kp[1];
        const uint4* vp = (const uint4*)(vg + (size_t)tid*DH);
        pv0 = vp[0]; pv1 = vp[1];
    }
    __syncthreads();

    uint32_t qa[2][4];
    #pragma unroll
    for (int mt = 0; mt < 2; ++mt)
        ldsm_x4(qa[mt], smem_u32(qs) +
            ((uint32_t)(wid*32 + mt*16 + (lane & 15))*24 + ((lane >> 4) & 1)*8)*2);

    float of[2][2][4];
    #pragma unroll
    for (int a = 0; a < 2; ++a)
        #pragma unroll
        for (int b = 0; b < 2; ++b)
            #pragma unroll
            for (int c = 0; c < 4; ++c) of[a][b][c] = 0.f;
    float lf[4] = {0.f, 0.f, 0.f, 0.f};

    const uint32_t kaddr = smem_u32(ks) +
        (uint32_t)(((lane >> 4) & 1)*8 + (lane & 7))*48 + ((lane >> 3) & 1)*16;
    const uint32_t vaddr = smem_u32(vs) + (uint32_t)(lane & 15)*48;
    const float z4[4] = {0.f, 0.f, 0.f, 0.f};

    for (int it = 0; it < 32; ++it) {
        const uint32_t buf = (uint32_t)(it & 1) * 6144;   // bytes per buffer
        __half* ksb = ks + (it & 1)*128*24;
        __half* vsb = vs + (it & 1)*128*24;
        *(uint4*)(ksb + tid*24)     = pk0;
        *(uint4*)(ksb + tid*24 + 8) = pk1;
        *(uint4*)(vsb + tid*24)     = pv0;
        *(uint4*)(vsb + tid*24 + 8) = pv1;
        if (it + 1 < 32) {
            const int kt = (it + 1) * 128;
            const uint4* kp = (const uint4*)(kg + (size_t)(kt + tid)*DH);
            pk0 = kp[0]; pk1 = kp[1];
            const uint4* vp = (const uint4*)(vg + (size_t)(kt + tid)*DH);
            pv0 = vp[0]; pv1 = vp[1];
        }
        __syncthreads();   // single barrier per tile (double-buffered)

        uint32_t lh[4] = {0u, 0u, 0u, 0u};   // f16x2 per-tile row-sum accum
        #pragma unroll
        for (int k4 = 0; k4 < 8; ++k4) {
            uint32_t kb[4];
            ldsm_x4(kb, kaddr + buf + (uint32_t)k4*768);
            uint32_t vb0[2], vb1[2];
            ldsm_x2t(vb0, vaddr + buf + (uint32_t)k4*768);
            ldsm_x2t(vb1, vaddr + buf + (uint32_t)k4*768 + 16);
            #pragma unroll
            for (int mt = 0; mt < 2; ++mt) {
                float sf[4];
                uint32_t pa[4];
                mma_fp16(sf, qa[mt], kb, z4);
                pa[0] = exp2_pack(sf[0], sf[1]);
                pa[1] = exp2_pack(sf[2], sf[3]);
                mma_fp16(sf, qa[mt], kb + 2, z4);
                pa[2] = exp2_pack(sf[0], sf[1]);
                pa[3] = exp2_pack(sf[2], sf[3]);
                lh[mt*2]   = hadd2u(lh[mt*2],   hadd2u(pa[0], pa[2]));
                lh[mt*2+1] = hadd2u(lh[mt*2+1], hadd2u(pa[1], pa[3]));
                mma_fp16(of[mt][0], pa, vb0, of[mt][0]);
                mma_fp16(of[mt][1], pa, vb1, of[mt][1]);
            }
        }
        #pragma unroll
        for (int i = 0; i < 4; ++i) {
            float2 f = __half22float2(*reinterpret_cast<__half2*>(&lh[i]));
            lf[i] += f.x + f.y;
        }
    }

    // epilogue: quad-reduce row sums (lanes in quad cover disjoint key slots)
    const int b = bh >> 3, h = bh & 7;
    #pragma unroll
    for (int mt = 0; mt < 2; ++mt) {
        #pragma unroll
        for (int rr = 0; rr < 2; ++rr) {
            float l = lf[mt*2 + rr];
            l += __shfl_xor_sync(0xffffffffu, l, 1);
            l += __shfl_xor_sync(0xffffffffu, l, 2);
            float inv = 1.f / l;
            int r = wid*32 + mt*16 + rr*8 + (lane >> 2);
            __half* dst = g_aoh + ((size_t)(b*NN) + n0 + r)*NC + h*16 + (lane & 3)*2;
            *(uint32_t*)dst       = f2h2(of[mt][0][rr*2]*inv, of[mt][0][rr*2+1]*inv);
            *(uint32_t*)(dst + 8) = f2h2(of[mt][1][rr*2]*inv, of[mt][1][rr*2+1]*inv);
        }
    }
}

// ======================= Kernel C: output projection + GN partials ==========
__global__ __launch_bounds__(128) void oproj_mma_kernel(
    const float* __restrict__ Wo, const float* __restrict__ bo)
{
    __shared__ __align__(16) __half as_[64*136];
    __shared__ __align__(16) __half ws[128*72];
    __shared__ float bs[128];
    __shared__ float ws1[4][8], ws2[4][8];

    const int bi = blockIdx.x >> 6;
    const int chunk = blockIdx.x & 63;
    const int n0 = chunk * 64;
    const int tid = threadIdx.x, lane = tid & 31, wid = tid >> 5;

    bs[tid] = bo[tid];

    for (int idx = tid; idx < 64*64; idx += 128) {
        int row = idx >> 6, u = idx & 63;
        uint32_t v = ((const uint32_t*)(g_aoh + ((size_t)(bi*NN) + n0 + row)*NC))[u];
        *(uint32_t*)(as_ + row*136 + u*2) = v;
    }
    __syncthreads();

    uint32_t qa[8][4];
    {
        uint32_t base = smem_u32(as_) +
            ((uint32_t)(wid*16 + (lane & 15))*136 + ((lane >> 4) & 1)*8)*2;
        #pragma unroll
        for (int k = 0; k < 8; ++k) ldsm_x4(qa[k], base + (uint32_t)k*32);
    }

    float of[16][4];
    #pragma unroll
    for (int t = 0; t < 16; ++t)
        #pragma unroll
        for (int j = 0; j < 4; ++j) of[t][j] = 0.f;

    for (int ph = 0; ph < 2; ++ph) {
        __syncthreads();
        for (int idx = tid; idx < 128*32; idx += 128) {
            int d = idx >> 5, cp = idx & 31;
            float2 wv = *(const float2*)(Wo + (size_t)d*NC + ph*64 + cp*2);
            *(uint32_t*)(ws + d*72 + cp*2) = f2h2(wv.x, wv.y);
        }
        __syncthreads();
        #pragma unroll
        for (int kk = 0; kk < 4; ++kk) {
            const int k = ph*4 + kk;
            uint32_t bbase = smem_u32(ws) +
                ((uint32_t)(((lane >> 4) & 1)*8 + (lane & 7))*72)*2 +
                (uint32_t)kk*32 + ((lane >> 3) & 1)*16;
            #pragma unroll
            for (int g = 0; g < 8; ++g) {
                uint32_t bb[4];
                ldsm_x4(bb, bbase + (uint32_t)g*16*72*2);
                mma_fp16(of[2*g],   qa[k], bb,     of[2*g]);
                mma_fp16(of[2*g+1], qa[k], bb + 2, of[2*g+1]);
            }
        }
    }

    // epilogue: add bias, store g_proj, accumulate per-group (sum, sumsq)
    const int r = wid*16 + (lane >> 2);
    float gs1[8], gs2[8];
    #pragma unroll
    for (int g = 0; g < 8; ++g) { gs1[g] = 0.f; gs2[g] = 0.f; }

    #pragma unroll
    for (int nt = 0; nt < 16; ++nt) {
        int c0 = nt*8 + (lane & 3)*2;
        float v0 = of[nt][0] + bs[c0];
        float v1 = of[nt][1] + bs[c0+1];
        float v2 = of[nt][2] + bs[c0];
        float v3 = of[nt][3] + bs[c0+1];
        float* d0 = g_proj + (size_t)(bi*NC + c0)*NN + n0 + r;
        float* d1 = g_proj + (size_t)(bi*NC + c0 + 1)*NN + n0 + r;
        d0[0] = v0; d1[0] = v1; d0[8] = v2; d1[8] = v3;
        int g = nt >> 1;
        gs1[g] += (v0 + v1) + (v2 + v3);
        gs2[g] += (v0*v0 + v1*v1) + (v2*v2 + v3*v3);
    }
    #pragma unroll
    for (int g = 0; g < 8; ++g) {
        float s1 = gs1[g], s2 = gs2[g];
        #pragma unroll
        for (int o = 16; o > 0; o >>= 1) {
            s1 += __shfl_xor_sync(0xffffffffu, s1, o);
            s2 += __shfl_xor_sync(0xffffffffu, s2, o);
        }
        if (lane == 0) { ws1[wid][g] = s1; ws2[wid][g] = s2; }
    }
    __syncthreads();
    if (tid < 8) {
        float S1 = ws1[0][tid] + ws1[1][tid] + ws1[2][tid] + ws1[3][tid];
        float S2 = ws2[0][tid] + ws2[1][tid] + ws2[2][tid] + ws2[3][tid];
        g_part[(bi*NG + tid)*64 + chunk] = make_float2(S1, S2);
    }
}

// ======================= Kernel E: GN apply + residual ======================
__global__ __launch_bounds__(256) void gnapply_kernel(
    const float* __restrict__ x,
    const float* __restrict__ gn_w, const float* __restrict__ gn_b,
    float* __restrict__ out)
{
    __shared__ float2 st_s;
    const int tid = threadIdx.x;
    if (tid < 32) {
        int bg = blockIdx.x >> 6;
        float S1 = 0.f, S2 = 0.f;
        #pragma unroll
        for (int c = tid; c < 64; c += 32) {
            float2 pp = g_part[bg*64 + c];
            S1 += pp.x; S2 += pp.y;
        }
        #pragma unroll
        for (int o = 16; o > 0; o >>= 1) {
            S1 += __shfl_xor_sync(0xffffffffu, S1, o);
            S2 += __shfl_xor_sync(0xffffffffu, S2, o);
        }
        if (tid == 0) {
            const float invn = 1.f / (16.f * NN);
            float mean = S1 * invn;
            float var  = S2 * invn - mean*mean;
            st_s = make_float2(mean, rsqrtf(var + GN_EPS));
        }
    }
    __syncthreads();
    float2 st = st_s;

    int i4 = blockIdx.x * 256 + tid;
    int fi = i4 * 4;
    int c  = (fi / NN) % NC;
    float w  = gn_w[c] * st.y;
    float bb = gn_b[c];
    float4 pv = ((const float4*)g_proj)[i4];
    float4 xv = ((const float4*)x)[i4];
    float4 o;
    o.x = (pv.x - st.x)*w + bb + xv.x;
    o.y = (pv.y - st.x)*w + bb + xv.y;
    o.z = (pv.z - st.x)*w + bb + xv.z;
    o.w = (pv.w - st.x)*w + bb + xv.w;
    ((float4*)out)[i4] = o;
}

// ======================= launch =============================================
extern "C" void kernel_launch(void* const* d_in, const int* in_sizes, int n_in,
                              void* d_out, int out_size)
{
    const float* x    = (const float*)d_in[0];
    const float* Wq   = (const float*)d_in[1];
    const float* bq   = (const float*)d_in[2];
    const float* Wk   = (const float*)d_in[3];
    const float* bk   = (const float*)d_in[4];
    const float* Wv   = (const float*)d_in[5];
    const float* bv   = (const float*)d_in[6];
    const float* Wo   = (const float*)d_in[7];
    const float* bo   = (const float*)d_in[8];
    const float* gn_w = (const float*)d_in[9];
    const float* gn_b = (const float*)d_in[10];
    float* out = (float*)d_out;

    qkv_mma_kernel<<<NB*64, 128>>>(x, Wq, bq, Wk, bk, Wv, bv);
    attn_mma_kernel<<<dim3(NB*NHD, NN/128), 128>>>();
    oproj_mma_kernel<<<NB*64, 128>>>(Wo, bo);
    gnapply_kernel<<<NB*NC*NN/4/256, 256>>>(x, gn_w, gn_b, out);
}

// round 7
// speedup vs baseline: 1.3480x; 1.3480x over previous
#include <cuda_runtime.h>
#include <cuda_fp16.h>
#include <cstdint>

#define NB 2
#define NC 128
#define NN 4096      // H*W
#define NHD 8        // heads
#define DH 16        // head dim
#define NG 8         // groupnorm groups
#define GN_EPS 1e-5f
#define CSCALE 0.36067376022224085f   // 0.25 * log2(e)

// ======================= PTX helpers (baseline sm_80+ features only) =======
__device__ __forceinline__ uint32_t smem_u32(const void* p) {
    uint32_t a;
    asm("{ .reg .u64 t; cvta.to.shared.u64 t, %1; cvt.u32.u64 %0, t; }" : "=r"(a) : "l"(p));
    return a;
}
__device__ __forceinline__ void ldsm_x4(uint32_t* r, uint32_t a) {
    asm volatile("ldmatrix.sync.aligned.m8n8.x4.shared.b16 {%0,%1,%2,%3}, [%4];"
        : "=r"(r[0]), "=r"(r[1]), "=r"(r[2]), "=r"(r[3]) : "r"(a));
}
__device__ __forceinline__ void ldsm_x2t(uint32_t* r, uint32_t a) {
    asm volatile("ldmatrix.sync.aligned.m8n8.x2.trans.shared.b16 {%0,%1}, [%2];"
        : "=r"(r[0]), "=r"(r[1]) : "r"(a));
}
__device__ __forceinline__ void mma_fp16(float* d, const uint32_t* a,
                                         const uint32_t* b, const float* c) {
    asm volatile("mma.sync.aligned.m16n8k16.row.col.f32.f16.f16.f32 "
        "{%0,%1,%2,%3},{%4,%5,%6,%7},{%8,%9},{%10,%11,%12,%13};"
        : "=f"(d[0]), "=f"(d[1]), "=f"(d[2]), "=f"(d[3])
        : "r"(a[0]), "r"(a[1]), "r"(a[2]), "r"(a[3]), "r"(b[0]), "r"(b[1]),
          "f"(c[0]), "f"(c[1]), "f"(c[2]), "f"(c[3]));
}
__device__ __forceinline__ uint32_t exp2_pack(float lo, float hi) {
    uint32_t h;
    asm("cvt.rn.f16x2.f32 %0, %1, %2;" : "=r"(h) : "f"(hi), "f"(lo));
    asm("ex2.approx.f16x2 %0, %1;" : "=r"(h) : "r"(h));
    return h;
}
__device__ __forceinline__ uint32_t hadd2u(uint32_t a, uint32_t b) {
    uint32_t d; asm("add.rn.f16x2 %0, %1, %2;" : "=r"(d) : "r"(a), "r"(b)); return d;
}
__device__ __forceinline__ uint32_t f2h2(float lo, float hi) {
    __half2 h = __floats2half2_rn(lo, hi);
    return *reinterpret_cast<uint32_t*>(&h);
}

// ======================= scratch =============================================
__device__ __half g_q  [NB*NHD*NN*DH];   // [b,h,n,d], pre-scaled by CSCALE
__device__ __half g_k  [NB*NHD*NN*DH];   // [b,h,n,d]
__device__ __half g_v  [NB*NHD*NN*DH];   // [b,h,n,d]
__device__ __half g_aoh[NB*NN*NC];       // attention out fp16, [b,n,c]
__device__ float  g_proj[NB*NC*NN];      // out-proj fp32, channel-major [b,c,n]
__device__ float2 g_part[NB*NG*64];      // GN partial (sum, sumsq) per token-chunk

// ======================= Kernel A: QKV projection on HMMA ===================
// grid (NB*64, 3): 64 tokens per CTA, blockIdx.y selects q/k/v (full wave).
__global__ __launch_bounds__(128) void qkv_mma_kernel(
    const float* __restrict__ x,
    const float* __restrict__ Wq, const float* __restrict__ bq,
    const float* __restrict__ Wk, const float* __restrict__ bk,
    const float* __restrict__ Wv, const float* __restrict__ bv)
{
    __shared__ __align__(16) __half xs[64*136];
    __shared__ __align__(16) __half ws[128*72];
    __shared__ float bs[128];

    const int bi = blockIdx.x >> 6;
    const int n0 = (blockIdx.x & 63) * 64;
    const int m  = blockIdx.y;
    const int tid = threadIdx.x, lane = tid & 31, wid = tid >> 5;

    const float* __restrict__ W    = (m == 0) ? Wq : (m == 1) ? Wk : Wv;
    const float* __restrict__ bias = (m == 0) ? bq : (m == 1) ? bk : bv;
    __half* __restrict__ outp      = (m == 0) ? g_q : (m == 1) ? g_k : g_v;
    const float s = (m == 0) ? CSCALE : 1.f;

    bs[tid] = bias[tid];

    {   // x tile [c=128][n=64] -> xs[n][c] fp16
        const int row = tid & 63, ch = (tid >> 6) * 64;
        const float* xp = x + (size_t)(bi*NC + ch)*NN + n0 + row;
        #pragma unroll 8
        for (int cc = 0; cc < 64; cc += 2) {
            float a = xp[(size_t)cc*NN];
            float b = xp[(size_t)(cc+1)*NN];
            *(uint32_t*)(xs + row*136 + ch + cc) = f2h2(a, b);
        }
    }
    __syncthreads();

    // A fragments for all 8 k-steps (reused across both W halves)
    uint32_t qa[8][4];
    {
        uint32_t base = smem_u32(xs) +
            ((uint32_t)(wid*16 + (lane & 15))*136 + ((lane >> 4) & 1)*8)*2;
        #pragma unroll
        for (int k = 0; k < 8; ++k) ldsm_x4(qa[k], base + (uint32_t)k*32);
    }

    float of[16][4];
    #pragma unroll
    for (int t = 0; t < 16; ++t)
        #pragma unroll
        for (int j = 0; j < 4; ++j) of[t][j] = 0.f;

    for (int ph = 0; ph < 2; ++ph) {
        __syncthreads();
        for (int idx = tid; idx < 128*32; idx += 128) {
            int d = idx >> 5, cp = idx & 31;
            float2 wv = *(const float2*)(W + (size_t)d*NC + ph*64 + cp*2);
            *(uint32_t*)(ws + d*72 + cp*2) = f2h2(wv.x, wv.y);
        }
        __syncthreads();
        #pragma unroll
        for (int kk = 0; kk < 4; ++kk) {
            const int k = ph*4 + kk;
            uint32_t bbase = smem_u32(ws) +
                ((uint32_t)(((lane >> 4) & 1)*8 + (lane & 7))*72)*2 +
                (uint32_t)kk*32 + ((lane >> 3) & 1)*16;
            #pragma unroll
            for (int g = 0; g < 8; ++g) {
                uint32_t bb[4];
                ldsm_x4(bb, bbase + (uint32_t)g*16*72*2);
                mma_fp16(of[2*g],   qa[k], bb,     of[2*g]);
                mma_fp16(of[2*g+1], qa[k], bb + 2, of[2*g+1]);
            }
        }
    }

    const int r = wid*16 + (lane >> 2);
    #pragma unroll
    for (int nt = 0; nt < 16; ++nt) {
        int c0 = nt*8 + (lane & 3)*2;
        int h = c0 >> 4, d = c0 & 15;
        __half* dst = outp + ((size_t)((bi*NHD + h)*NN) + n0 + r)*DH + d;
        *(uint32_t*)dst          = f2h2((of[nt][0]+bs[c0])*s, (of[nt][1]+bs[c0+1])*s);
        *(uint32_t*)(dst + 8*DH) = f2h2((of[nt][2]+bs[c0])*s, (of[nt][3]+bs[c0+1])*s);
    }
}

// ======================= Kernel B: HMMA flash attention (R5 structure) ======
__global__ __launch_bounds__(128) void attn_mma_kernel()
{
    __shared__ __align__(16) __half qs[128*24];
    __shared__ __align__(16) __half ks[128*24];
    __shared__ __align__(16) __half vs[128*24];

    const int bh = blockIdx.x;
    const int n0 = blockIdx.y * 128;
    const int tid = threadIdx.x, lane = tid & 31, wid = tid >> 5;

    const __half* __restrict__ qg = g_q + (size_t)bh*NN*DH;
    const __half* __restrict__ kg = g_k + (size_t)bh*NN*DH;
    const __half* __restrict__ vg = g_v + (size_t)bh*NN*DH;

    {   // Q tile: one row per thread
        const uint4* q4 = (const uint4*)(qg + (size_t)(n0 + tid)*DH);
        *(uint4*)(qs + tid*24)     = q4[0];
        *(uint4*)(qs + tid*24 + 8) = q4[1];
    }
    uint4 pk0, pk1, pv0, pv1;
    {
        const uint4* kp = (const uint4*)(kg + (size_t)tid*DH);
        pk0 = kp[0]; pk1 = kp[1];
        const uint4* vp = (const uint4*)(vg + (size_t)tid*DH);
        pv0 = vp[0]; pv1 = vp[1];
    }
    __syncthreads();

    uint32_t qa[2][4];
    #pragma unroll
    for (int mt = 0; mt < 2; ++mt)
        ldsm_x4(qa[mt], smem_u32(qs) +
            ((uint32_t)(wid*32 + mt*16 + (lane & 15))*24 + ((lane >> 4) & 1)*8)*2);

    float of[2][2][4];
    #pragma unroll
    for (int a = 0; a < 2; ++a)
        #pragma unroll
        for (int b = 0; b < 2; ++b)
            #pragma unroll
            for (int c = 0; c < 4; ++c) of[a][b][c] = 0.f;
    float lf[4] = {0.f, 0.f, 0.f, 0.f};

    const uint32_t kaddr = smem_u32(ks) +
        (uint32_t)(((lane >> 4) & 1)*8 + (lane & 7))*48 + ((lane >> 3) & 1)*16;
    const uint32_t vaddr = smem_u32(vs) + (uint32_t)(lane & 15)*48;
    const float z4[4] = {0.f, 0.f, 0.f, 0.f};

    for (int it = 0; it < 32; ++it) {
        __syncthreads();
        *(uint4*)(ks + tid*24)     = pk0;
        *(uint4*)(ks + tid*24 + 8) = pk1;
        *(uint4*)(vs + tid*24)     = pv0;
        *(uint4*)(vs + tid*24 + 8) = pv1;
        if (it + 1 < 32) {
            const int kt = (it + 1) * 128;
            const uint4* kp = (const uint4*)(kg + (size_t)(kt + tid)*DH);
            pk0 = kp[0]; pk1 = kp[1];
            const uint4* vp = (const uint4*)(vg + (size_t)(kt + tid)*DH);
            pv0 = vp[0]; pv1 = vp[1];
        }
        __syncthreads();

        uint32_t lh[4] = {0u, 0u, 0u, 0u};   // f16x2 per-tile row-sum accum
        #pragma unroll
        for (int k4 = 0; k4 < 8; ++k4) {
            uint32_t kb[4];
            ldsm_x4(kb, kaddr + (uint32_t)k4*768);
            uint32_t vb0[2], vb1[2];
            ldsm_x2t(vb0, vaddr + (uint32_t)k4*768);
            ldsm_x2t(vb1, vaddr + (uint32_t)k4*768 + 16);
            #pragma unroll
            for (int mt = 0; mt < 2; ++mt) {
                float sf[4];
                uint32_t pa[4];
                mma_fp16(sf, qa[mt], kb, z4);
                pa[0] = exp2_pack(sf[0], sf[1]);
                pa[1] = exp2_pack(sf[2], sf[3]);
                mma_fp16(sf, qa[mt], kb + 2, z4);
                pa[2] = exp2_pack(sf[0], sf[1]);
                pa[3] = exp2_pack(sf[2], sf[3]);
                lh[mt*2]   = hadd2u(lh[mt*2],   hadd2u(pa[0], pa[2]));
                lh[mt*2+1] = hadd2u(lh[mt*2+1], hadd2u(pa[1], pa[3]));
                mma_fp16(of[mt][0], pa, vb0, of[mt][0]);
                mma_fp16(of[mt][1], pa, vb1, of[mt][1]);
            }
        }
        #pragma unroll
        for (int i = 0; i < 4; ++i) {
            float2 f = __half22float2(*reinterpret_cast<__half2*>(&lh[i]));
            lf[i] += f.x + f.y;
        }
    }

    // epilogue: quad-reduce row sums (lanes in quad cover disjoint key slots)
    const int b = bh >> 3, h = bh & 7;
    #pragma unroll
    for (int mt = 0; mt < 2; ++mt) {
        #pragma unroll
        for (int rr = 0; rr < 2; ++rr) {
            float l = lf[mt*2 + rr];
            l += __shfl_xor_sync(0xffffffffu, l, 1);
            l += __shfl_xor_sync(0xffffffffu, l, 2);
            float inv = 1.f / l;
            int r = wid*32 + mt*16 + rr*8 + (lane >> 2);
            __half* dst = g_aoh + ((size_t)(b*NN) + n0 + r)*NC + h*16 + (lane & 3)*2;
            *(uint32_t*)dst       = f2h2(of[mt][0][rr*2]*inv, of[mt][0][rr*2+1]*inv);
            *(uint32_t*)(dst + 8) = f2h2(of[mt][1][rr*2]*inv, of[mt][1][rr*2+1]*inv);
        }
    }
}

// ======================= Kernel C: output projection + GN partials ==========
__global__ __launch_bounds__(128) void oproj_mma_kernel(
    const float* __restrict__ Wo, const float* __restrict__ bo)
{
    __shared__ __align__(16) __half as_[64*136];
    __shared__ __align__(16) __half ws[128*72];
    __shared__ float bs[128];
    __shared__ float ws1[4][8], ws2[4][8];

    const int bi = blockIdx.x >> 6;
    const int chunk = blockIdx.x & 63;
    const int n0 = chunk * 64;
    const int tid = threadIdx.x, lane = tid & 31, wid = tid >> 5;

    bs[tid] = bo[tid];

    for (int idx = tid; idx < 64*64; idx += 128) {
        int row = idx >> 6, u = idx & 63;
        uint32_t v = ((const uint32_t*)(g_aoh + ((size_t)(bi*NN) + n0 + row)*NC))[u];
        *(uint32_t*)(as_ + row*136 + u*2) = v;
    }
    __syncthreads();

    uint32_t qa[8][4];
    {
        uint32_t base = smem_u32(as_) +
            ((uint32_t)(wid*16 + (lane & 15))*136 + ((lane >> 4) & 1)*8)*2;
        #pragma unroll
        for (int k = 0; k < 8; ++k) ldsm_x4(qa[k], base + (uint32_t)k*32);
    }

    float of[16][4];
    #pragma unroll
    for (int t = 0; t < 16; ++t)
        #pragma unroll
        for (int j = 0; j < 4; ++j) of[t][j] = 0.f;

    for (int ph = 0; ph < 2; ++ph) {
        __syncthreads();
        for (int idx = tid; idx < 128*32; idx += 128) {
            int d = idx >> 5, cp = idx & 31;
            float2 wv = *(const float2*)(Wo + (size_t)d*NC + ph*64 + cp*2);
            *(uint32_t*)(ws + d*72 + cp*2) = f2h2(wv.x, wv.y);
        }
        __syncthreads();
        #pragma unroll
        for (int kk = 0; kk < 4; ++kk) {
            const int k = ph*4 + kk;
            uint32_t bbase = smem_u32(ws) +
                ((uint32_t)(((lane >> 4) & 1)*8 + (lane & 7))*72)*2 +
                (uint32_t)kk*32 + ((lane >> 3) & 1)*16;
            #pragma unroll
            for (int g = 0; g < 8; ++g) {
                uint32_t bb[4];
                ldsm_x4(bb, bbase + (uint32_t)g*16*72*2);
                mma_fp16(of[2*g],   qa[k], bb,     of[2*g]);
                mma_fp16(of[2*g+1], qa[k], bb + 2, of[2*g+1]);
            }
        }
    }

    // epilogue: add bias, store g_proj, accumulate per-group (sum, sumsq)
    const int r = wid*16 + (lane >> 2);
    float gs1[8], gs2[8];
    #pragma unroll
    for (int g = 0; g < 8; ++g) { gs1[g] = 0.f; gs2[g] = 0.f; }

    #pragma unroll
    for (int nt = 0; nt < 16; ++nt) {
        int c0 = nt*8 + (lane & 3)*2;
        float v0 = of[nt][0] + bs[c0];
        float v1 = of[nt][1] + bs[c0+1];
        float v2 = of[nt][2] + bs[c0];
        float v3 = of[nt][3] + bs[c0+1];
        float* d0 = g_proj + (size_t)(bi*NC + c0)*NN + n0 + r;
        float* d1 = g_proj + (size_t)(bi*NC + c0 + 1)*NN + n0 + r;
        d0[0] = v0; d1[0] = v1; d0[8] = v2; d1[8] = v3;
        int g = nt >> 1;
        gs1[g] += (v0 + v1) + (v2 + v3);
        gs2[g] += (v0*v0 + v1*v1) + (v2*v2 + v3*v3);
    }
    #pragma unroll
    for (int g = 0; g < 8; ++g) {
        float s1 = gs1[g], s2 = gs2[g];
        #pragma unroll
        for (int o = 16; o > 0; o >>= 1) {
            s1 += __shfl_xor_sync(0xffffffffu, s1, o);
            s2 += __shfl_xor_sync(0xffffffffu, s2, o);
        }
        if (lane == 0) { ws1[wid][g] = s1; ws2[wid][g] = s2; }
    }
    __syncthreads();
    if (tid < 8) {
        float S1 = ws1[0][tid] + ws1[1][tid] + ws1[2][tid] + ws1[3][tid];
        float S2 = ws2[0][tid] + ws2[1][tid] + ws2[2][tid] + ws2[3][tid];
        g_part[(bi*NG + tid)*64 + chunk] = make_float2(S1, S2);
    }
}

// ======================= Kernel E: GN apply + residual ======================
__global__ __launch_bounds__(256) void gnapply_kernel(
    const float* __restrict__ x,
    const float* __restrict__ gn_w, const float* __restrict__ gn_b,
    float* __restrict__ out)
{
    __shared__ float2 st_s;
    const int tid = threadIdx.x;
    if (tid < 32) {
        int bg = blockIdx.x >> 6;
        float S1 = 0.f, S2 = 0.f;
        #pragma unroll
        for (int c = tid; c < 64; c += 32) {
            float2 pp = g_part[bg*64 + c];
            S1 += pp.x; S2 += pp.y;
        }
        #pragma unroll
        for (int o = 16; o > 0; o >>= 1) {
            S1 += __shfl_xor_sync(0xffffffffu, S1, o);
            S2 += __shfl_xor_sync(0xffffffffu, S2, o);
        }
        if (tid == 0) {
            const float invn = 1.f / (16.f * NN);
            float mean = S1 * invn;
            float var  = S2 * invn - mean*mean;
            st_s = make_float2(mean, rsqrtf(var + GN_EPS));
        }
    }
    __syncthreads();
    float2 st = st_s;

    int i4 = blockIdx.x * 256 + tid;
    int fi = i4 * 4;
    int c  = (fi / NN) % NC;
    float w  = gn_w[c] * st.y;
    float bb = gn_b[c];
    float4 pv = ((const float4*)g_proj)[i4];
    float4 xv = ((const float4*)x)[i4];
    float4 o;
    o.x = (pv.x - st.x)*w + bb + xv.x;
    o.y = (pv.y - st.x)*w + bb + xv.y;
    o.z = (pv.z - st.x)*w + bb + xv.z;
    o.w = (pv.w - st.x)*w + bb + xv.w;
    ((float4*)out)[i4] = o;
}

// ======================= launch =============================================
extern "C" void kernel_launch(void* const* d_in, const int* in_sizes, int n_in,
                              void* d_out, int out_size)
{
    const float* x    = (const float*)d_in[0];
    const float* Wq   = (const float*)d_in[1];
    const float* bq   = (const float*)d_in[2];
    const float* Wk   = (const float*)d_in[3];
    const float* bk   = (const float*)d_in[4];
    const float* Wv   = (const float*)d_in[5];
    const float* bv   = (const float*)d_in[6];
    const float* Wo   = (const float*)d_in[7];
    const float* bo   = (const float*)d_in[8];
    const float* gn_w = (const float*)d_in[9];
    const float* gn_b = (const float*)d_in[10];
    float* out = (float*)d_out;

    qkv_mma_kernel<<<dim3(NB*64, 3), 128>>>(x, Wq, bq, Wk, bk, Wv, bv);
    attn_mma_kernel<<<dim3(NB*NHD, NN/128), 128>>>();
    oproj_mma_kernel<<<NB*64, 128>>>(Wo, bo);
    gnapply_kernel<<<NB*NC*NN/4/256, 256>>>(x, gn_w, gn_b, out);
}

// round 8
// speedup vs baseline: 1.3823x; 1.0255x over previous
#include <cuda_runtime.h>
#include <cuda_fp16.h>
#include <cstdint>

#define NB 2
#define NC 128
#define NN 4096      // H*W
#define NHD 8        // heads
#define DH 16        // head dim
#define NG 8         // groupnorm groups
#define GN_EPS 1e-5f
#define CSCALE 0.36067376022224085f   // 0.25 * log2(e)

// ======================= PTX helpers (baseline sm_80+ features only) =======
__device__ __forceinline__ uint32_t smem_u32(const void* p) {
    uint32_t a;
    asm("{ .reg .u64 t; cvta.to.shared.u64 t, %1; cvt.u32.u64 %0, t; }" : "=r"(a) : "l"(p));
    return a;
}
__device__ __forceinline__ void ldsm_x4(uint32_t* r, uint32_t a) {
    asm volatile("ldmatrix.sync.aligned.m8n8.x4.shared.b16 {%0,%1,%2,%3}, [%4];"
        : "=r"(r[0]), "=r"(r[1]), "=r"(r[2]), "=r"(r[3]) : "r"(a));
}
__device__ __forceinline__ void ldsm_x2t(uint32_t* r, uint32_t a) {
    asm volatile("ldmatrix.sync.aligned.m8n8.x2.trans.shared.b16 {%0,%1}, [%2];"
        : "=r"(r[0]), "=r"(r[1]) : "r"(a));
}
__device__ __forceinline__ void mma_fp16(float* d, const uint32_t* a,
                                         const uint32_t* b, const float* c) {
    asm volatile("mma.sync.aligned.m16n8k16.row.col.f32.f16.f16.f32 "
        "{%0,%1,%2,%3},{%4,%5,%6,%7},{%8,%9},{%10,%11,%12,%13};"
        : "=f"(d[0]), "=f"(d[1]), "=f"(d[2]), "=f"(d[3])
        : "r"(a[0]), "r"(a[1]), "r"(a[2]), "r"(a[3]), "r"(b[0]), "r"(b[1]),
          "f"(c[0]), "f"(c[1]), "f"(c[2]), "f"(c[3]));
}
__device__ __forceinline__ uint32_t exp2_pack(float lo, float hi) {
    uint32_t h;
    asm("cvt.rn.f16x2.f32 %0, %1, %2;" : "=r"(h) : "f"(hi), "f"(lo));
    asm("ex2.approx.f16x2 %0, %1;" : "=r"(h) : "r"(h));
    return h;
}
__device__ __forceinline__ uint32_t hadd2u(uint32_t a, uint32_t b) {
    uint32_t d; asm("add.rn.f16x2 %0, %1, %2;" : "=r"(d) : "r"(a), "r"(b)); return d;
}
__device__ __forceinline__ uint32_t f2h2(float lo, float hi) {
    __half2 h = __floats2half2_rn(lo, hi);
    return *reinterpret_cast<uint32_t*>(&h);
}

// ======================= scratch =============================================
__device__ __half g_q  [NB*NHD*NN*DH];   // [b,h,n,d], pre-scaled by CSCALE
__device__ __half g_k  [NB*NHD*NN*DH];   // [b,h,n,d]
__device__ __half g_v  [NB*NHD*NN*DH];   // [b,h,n,d]
__device__ __half g_aoh[NB*NN*NC];       // attention out fp16, [b,n,c]
__device__ float  g_proj[NB*NC*NN];      // out-proj fp32, channel-major [b,c,n]
__device__ float2 g_part[NB*NG*64];      // GN partial (sum, sumsq) per token-chunk
__device__ __align__(16) __half g_wh[4*NC*NC];  // fp16 weights: Wq,Wk,Wv,Wo

// ======================= Kernel W: weight fp32 -> fp16 once =================
__global__ __launch_bounds__(256) void wcvt_kernel(
    const float* __restrict__ Wq, const float* __restrict__ Wk,
    const float* __restrict__ Wv, const float* __restrict__ Wo)
{
    int i = blockIdx.x * 256 + threadIdx.x;     // float2 units, 0..32767
    int m = i >> 13, o = i & 8191;
    const float* src = (m == 0) ? Wq : (m == 1) ? Wk : (m == 2) ? Wv : Wo;
    float2 v = ((const float2*)src)[o];
    *(uint32_t*)(g_wh + (size_t)m*16384 + o*2) = f2h2(v.x, v.y);
}

// ======================= Kernel A: QKV projection on HMMA ===================
// grid (NB*64, 3): 64 tokens per CTA, blockIdx.y selects q/k/v (full wave).
__global__ __launch_bounds__(128) void qkv_mma_kernel(
    const float* __restrict__ x,
    const float* __restrict__ bq, const float* __restrict__ bk,
    const float* __restrict__ bv)
{
    __shared__ __align__(16) __half xs[64*136];
    __shared__ __align__(16) __half ws[128*72];
    __shared__ float bs[128];

    const int bi = blockIdx.x >> 6;
    const int n0 = (blockIdx.x & 63) * 64;
    const int m  = blockIdx.y;
    const int tid = threadIdx.x, lane = tid & 31, wid = tid >> 5;

    const __half* __restrict__ wsrc = g_wh + (size_t)m*16384;
    const float* __restrict__ bias  = (m == 0) ? bq : (m == 1) ? bk : bv;
    __half* __restrict__ outp       = (m == 0) ? g_q : (m == 1) ? g_k : g_v;
    const float s = (m == 0) ? CSCALE : 1.f;

    bs[tid] = bias[tid];

    {   // x tile [c=128][n=64] -> xs[n][c] fp16
        const int row = tid & 63, ch = (tid >> 6) * 64;
        const float* xp = x + (size_t)(bi*NC + ch)*NN + n0 + row;
        #pragma unroll 8
        for (int cc = 0; cc < 64; cc += 2) {
            float a = xp[(size_t)cc*NN];
            float b = xp[(size_t)(cc+1)*NN];
            *(uint32_t*)(xs + row*136 + ch + cc) = f2h2(a, b);
        }
    }
    __syncthreads();

    uint32_t qa[8][4];
    {
        uint32_t base = smem_u32(xs) +
            ((uint32_t)(wid*16 + (lane & 15))*136 + ((lane >> 4) & 1)*8)*2;
        #pragma unroll
        for (int k = 0; k < 8; ++k) ldsm_x4(qa[k], base + (uint32_t)k*32);
    }

    float of[16][4];
    #pragma unroll
    for (int t = 0; t < 16; ++t)
        #pragma unroll
        for (int j = 0; j < 4; ++j) of[t][j] = 0.f;

    for (int ph = 0; ph < 2; ++ph) {
        __syncthreads();
        #pragma unroll
        for (int i = tid; i < 1024; i += 128) {    // fp16 weight copy (no cvt)
            int d = i >> 3, u = i & 7;
            *(uint4*)(ws + d*72 + u*8) = *(const uint4*)(wsrc + d*128 + ph*64 + u*8);
        }
        __syncthreads();
        #pragma unroll
        for (int kk = 0; kk < 4; ++kk) {
            const int k = ph*4 + kk;
            uint32_t bbase = smem_u32(ws) +
                ((uint32_t)(((lane >> 4) & 1)*8 + (lane & 7))*72)*2 +
                (uint32_t)kk*32 + ((lane >> 3) & 1)*16;
            #pragma unroll
            for (int g = 0; g < 8; ++g) {
                uint32_t bb[4];
                ldsm_x4(bb, bbase + (uint32_t)g*16*72*2);
                mma_fp16(of[2*g],   qa[k], bb,     of[2*g]);
                mma_fp16(of[2*g+1], qa[k], bb + 2, of[2*g+1]);
            }
        }
    }

    const int r = wid*16 + (lane >> 2);
    #pragma unroll
    for (int nt = 0; nt < 16; ++nt) {
        int c0 = nt*8 + (lane & 3)*2;
        int h = c0 >> 4, d = c0 & 15;
        __half* dst = outp + ((size_t)((bi*NHD + h)*NN) + n0 + r)*DH + d;
        *(uint32_t*)dst          = f2h2((of[nt][0]+bs[c0])*s, (of[nt][1]+bs[c0+1])*s);
        *(uint32_t*)(dst + 8*DH) = f2h2((of[nt][2]+bs[c0])*s, (of[nt][3]+bs[c0+1])*s);
    }
}

// ======================= Kernel B: HMMA flash attention (pipelined) =========
// QK mma of k4+1 issued BEFORE exp/PV of k4: tensor overlaps MUFU.
__global__ __launch_bounds__(128) void attn_mma_kernel()
{
    __shared__ __align__(16) __half qs[128*24];
    __shared__ __align__(16) __half ks[128*24];
    __shared__ __align__(16) __half vs[128*24];

    const int bh = blockIdx.x;
    const int n0 = blockIdx.y * 128;
    const int tid = threadIdx.x, lane = tid & 31, wid = tid >> 5;

    const __half* __restrict__ qg = g_q + (size_t)bh*NN*DH;
    const __half* __restrict__ kg = g_k + (size_t)bh*NN*DH;
    const __half* __restrict__ vg = g_v + (size_t)bh*NN*DH;

    {
        const uint4* q4 = (const uint4*)(qg + (size_t)(n0 + tid)*DH);
        *(uint4*)(qs + tid*24)     = q4[0];
        *(uint4*)(qs + tid*24 + 8) = q4[1];
    }
    uint4 pk0, pk1, pv0, pv1;
    {
        const uint4* kp = (const uint4*)(kg + (size_t)tid*DH);
        pk0 = kp[0]; pk1 = kp[1];
        const uint4* vp = (const uint4*)(vg + (size_t)tid*DH);
        pv0 = vp[0]; pv1 = vp[1];
    }
    __syncthreads();

    uint32_t qa[2][4];
    #pragma unroll
    for (int mt = 0; mt < 2; ++mt)
        ldsm_x4(qa[mt], smem_u32(qs) +
            ((uint32_t)(wid*32 + mt*16 + (lane & 15))*24 + ((lane >> 4) & 1)*8)*2);

    float of[2][2][4];
    #pragma unroll
    for (int a = 0; a < 2; ++a)
        #pragma unroll
        for (int b = 0; b < 2; ++b)
            #pragma unroll
            for (int c = 0; c < 4; ++c) of[a][b][c] = 0.f;
    float lf[4] = {0.f, 0.f, 0.f, 0.f};

    const uint32_t kaddr = smem_u32(ks) +
        (uint32_t)(((lane >> 4) & 1)*8 + (lane & 7))*48 + ((lane >> 3) & 1)*16;
    const uint32_t vaddr = smem_u32(vs) + (uint32_t)(lane & 15)*48;
    const float z4[4] = {0.f, 0.f, 0.f, 0.f};

    for (int it = 0; it < 32; ++it) {
        __syncthreads();
        *(uint4*)(ks + tid*24)     = pk0;
        *(uint4*)(ks + tid*24 + 8) = pk1;
        *(uint4*)(vs + tid*24)     = pv0;
        *(uint4*)(vs + tid*24 + 8) = pv1;
        if (it + 1 < 32) {
            const int kt = (it + 1) * 128;
            const uint4* kp = (const uint4*)(kg + (size_t)(kt + tid)*DH);
            pk0 = kp[0]; pk1 = kp[1];
            const uint4* vp = (const uint4*)(vg + (size_t)(kt + tid)*DH);
            pv0 = vp[0]; pv1 = vp[1];
        }
        __syncthreads();

        uint32_t lh[4] = {0u, 0u, 0u, 0u};
        uint32_t kb[4];
        float sc[16];                       // S for current k4: [mt*8 + half*4 + j]
        ldsm_x4(kb, kaddr);
        mma_fp16(sc+0,  qa[0], kb,     z4);
        mma_fp16(sc+4,  qa[0], kb + 2, z4);
        mma_fp16(sc+8,  qa[1], kb,     z4);
        mma_fp16(sc+12, qa[1], kb + 2, z4);

        #pragma unroll
        for (int k4 = 0; k4 < 8; ++k4) {
            float sn[16];
            if (k4 < 7) {                  // QK(k4+1) on tensor, overlaps exp(k4)
                ldsm_x4(kb, kaddr + (uint32_t)(k4+1)*768);
                mma_fp16(sn+0,  qa[0], kb,     z4);
                mma_fp16(sn+4,  qa[0], kb + 2, z4);
                mma_fp16(sn+8,  qa[1], kb,     z4);
                mma_fp16(sn+12, qa[1], kb + 2, z4);
            }
            uint32_t vb0[2], vb1[2];
            ldsm_x2t(vb0, vaddr + (uint32_t)k4*768);
            ldsm_x2t(vb1, vaddr + (uint32_t)k4*768 + 16);
            #pragma unroll
            for (int mt = 0; mt < 2; ++mt) {
                uint32_t pa[4];
                pa[0] = exp2_pack(sc[mt*8+0], sc[mt*8+1]);
                pa[1] = exp2_pack(sc[mt*8+2], sc[mt*8+3]);
                pa[2] = exp2_pack(sc[mt*8+4], sc[mt*8+5]);
                pa[3] = exp2_pack(sc[mt*8+6], sc[mt*8+7]);
                lh[mt*2]   = hadd2u(lh[mt*2],   hadd2u(pa[0], pa[2]));
                lh[mt*2+1] = hadd2u(lh[mt*2+1], hadd2u(pa[1], pa[3]));
                mma_fp16(of[mt][0], pa, vb0, of[mt][0]);
                mma_fp16(of[mt][1], pa, vb1, of[mt][1]);
            }
            if (k4 < 7) {
                #pragma unroll
                for (int j = 0; j < 16; ++j) sc[j] = sn[j];
            }
        }
        #pragma unroll
        for (int i = 0; i < 4; ++i) {
            float2 f = __half22float2(*reinterpret_cast<__half2*>(&lh[i]));
            lf[i] += f.x + f.y;
        }
    }

    const int b = bh >> 3, h = bh & 7;
    #pragma unroll
    for (int mt = 0; mt < 2; ++mt) {
        #pragma unroll
        for (int rr = 0; rr < 2; ++rr) {
            float l = lf[mt*2 + rr];
            l += __shfl_xor_sync(0xffffffffu, l, 1);
            l += __shfl_xor_sync(0xffffffffu, l, 2);
            float inv = 1.f / l;
            int r = wid*32 + mt*16 + rr*8 + (lane >> 2);
            __half* dst = g_aoh + ((size_t)(b*NN) + n0 + r)*NC + h*16 + (lane & 3)*2;
            *(uint32_t*)dst       = f2h2(of[mt][0][rr*2]*inv, of[mt][0][rr*2+1]*inv);
            *(uint32_t*)(dst + 8) = f2h2(of[mt][1][rr*2]*inv, of[mt][1][rr*2+1]*inv);
        }
    }
}

// ======================= Kernel C: output projection + GN partials ==========
__global__ __launch_bounds__(128) void oproj_mma_kernel(const float* __restrict__ bo)
{
    __shared__ __align__(16) __half as_[64*136];
    __shared__ __align__(16) __half ws[128*72];
    __shared__ float bs[128];
    __shared__ float ws1[4][8], ws2[4][8];

    const int bi = blockIdx.x >> 6;
    const int chunk = blockIdx.x & 63;
    const int n0 = chunk * 64;
    const int tid = threadIdx.x, lane = tid & 31, wid = tid >> 5;
    const __half* __restrict__ wsrc = g_wh + (size_t)3*16384;

    bs[tid] = bo[tid];

    for (int idx = tid; idx < 64*64; idx += 128) {
        int row = idx >> 6, u = idx & 63;
        uint32_t v = ((const uint32_t*)(g_aoh + ((size_t)(bi*NN) + n0 + row)*NC))[u];
        *(uint32_t*)(as_ + row*136 + u*2) = v;
    }
    __syncthreads();

    uint32_t qa[8][4];
    {
        uint32_t base = smem_u32(as_) +
            ((uint32_t)(wid*16 + (lane & 15))*136 + ((lane >> 4) & 1)*8)*2;
        #pragma unroll
        for (int k = 0; k < 8; ++k) ldsm_x4(qa[k], base + (uint32_t)k*32);
    }

    float of[16][4];
    #pragma unroll
    for (int t = 0; t < 16; ++t)
        #pragma unroll
        for (int j = 0; j < 4; ++j) of[t][j] = 0.f;

    for (int ph = 0; ph < 2; ++ph) {
        __syncthreads();
        #pragma unroll
        for (int i = tid; i < 1024; i += 128) {
            int d = i >> 3, u = i & 7;
            *(uint4*)(ws + d*72 + u*8) = *(const uint4*)(wsrc + d*128 + ph*64 + u*8);
        }
        __syncthreads();
        #pragma unroll
        for (int kk = 0; kk < 4; ++kk) {
            const int k = ph*4 + kk;
            uint32_t bbase = smem_u32(ws) +
                ((uint32_t)(((lane >> 4) & 1)*8 + (lane & 7))*72)*2 +
                (uint32_t)kk*32 + ((lane >> 3) & 1)*16;
            #pragma unroll
            for (int g = 0; g < 8; ++g) {
                uint32_t bb[4];
                ldsm_x4(bb, bbase + (uint32_t)g*16*72*2);
                mma_fp16(of[2*g],   qa[k], bb,     of[2*g]);
                mma_fp16(of[2*g+1], qa[k], bb + 2, of[2*g+1]);
            }
        }
    }

    const int r = wid*16 + (lane >> 2);
    float gs1[8], gs2[8];
    #pragma unroll
    for (int g = 0; g < 8; ++g) { gs1[g] = 0.f; gs2[g] = 0.f; }

    #pragma unroll
    for (int nt = 0; nt < 16; ++nt) {
        int c0 = nt*8 + (lane & 3)*2;
        float v0 = of[nt][0] + bs[c0];
        float v1 = of[nt][1] + bs[c0+1];
        float v2 = of[nt][2] + bs[c0];
        float v3 = of[nt][3] + bs[c0+1];
        float* d0 = g_proj + (size_t)(bi*NC + c0)*NN + n0 + r;
        float* d1 = g_proj + (size_t)(bi*NC + c0 + 1)*NN + n0 + r;
        d0[0] = v0; d1[0] = v1; d0[8] = v2; d1[8] = v3;
        int g = nt >> 1;
        gs1[g] += (v0 + v1) + (v2 + v3);
        gs2[g] += (v0*v0 + v1*v1) + (v2*v2 + v3*v3);
    }
    #pragma unroll
    for (int g = 0; g < 8; ++g) {
        float s1 = gs1[g], s2 = gs2[g];
        #pragma unroll
        for (int o = 16; o > 0; o >>= 1) {
            s1 += __shfl_xor_sync(0xffffffffu, s1, o);
            s2 += __shfl_xor_sync(0xffffffffu, s2, o);
        }
        if (lane == 0) { ws1[wid][g] = s1; ws2[wid][g] = s2; }
    }
    __syncthreads();
    if (tid < 8) {
        float S1 = ws1[0][tid] + ws1[1][tid] + ws1[2][tid] + ws1[3][tid];
        float S2 = ws2[0][tid] + ws2[1][tid] + ws2[2][tid] + ws2[3][tid];
        g_part[(bi*NG + tid)*64 + chunk] = make_float2(S1, S2);
    }
}

// ======================= Kernel E: GN apply + residual (MLP 4) ==============
__global__ __launch_bounds__(256) void gnapply_kernel(
    const float* __restrict__ x,
    const float* __restrict__ gn_w, const float* __restrict__ gn_b,
    float* __restrict__ out)
{
    __shared__ float2 st_s;
    const int tid = threadIdx.x;
    if (tid < 32) {
        int bg = blockIdx.x >> 5;            // 32 blocks per (b,g)
        float S1 = 0.f, S2 = 0.f;
        #pragma unroll
        for (int c = tid; c < 64; c += 32) {
            float2 pp = g_part[bg*64 + c];
            S1 += pp.x; S2 += pp.y;
        }
        #pragma unroll
        for (int o = 16; o > 0; o >>= 1) {
            S1 += __shfl_xor_sync(0xffffffffu, S1, o);
            S2 += __shfl_xor_sync(0xffffffffu, S2, o);
        }
        if (tid == 0) {
            const float invn = 1.f / (16.f * NN);
            float mean = S1 * invn;
            float var  = S2 * invn - mean*mean;
            st_s = make_float2(mean, rsqrtf(var + GN_EPS));
        }
    }

    int ia = blockIdx.x * 512 + tid;
    int ib = ia + 256;
    float4 pva = ((const float4*)g_proj)[ia];
    float4 xva = ((const float4*)x)[ia];
    float4 pvb = ((const float4*)g_proj)[ib];
    float4 xvb = ((const float4*)x)[ib];
    int ca = (ia >> 10) & 127, cb = (ib >> 10) & 127;
    float gwa = gn_w[ca], gba = gn_b[ca];
    float gwb = gn_w[cb], gbb = gn_b[cb];

    __syncthreads();
    float2 st = st_s;
    float wa = gwa * st.y, wb = gwb * st.y;

    float4 oa, ob;
    oa.x = (pva.x - st.x)*wa + gba + xva.x;
    oa.y = (pva.y - st.x)*wa + gba + xva.y;
    oa.z = (pva.z - st.x)*wa + gba + xva.z;
    oa.w = (pva.w - st.x)*wa + gba + xva.w;
    ob.x = (pvb.x - st.x)*wb + gbb + xvb.x;
    ob.y = (pvb.y - st.x)*wb + gbb + xvb.y;
    ob.z = (pvb.z - st.x)*wb + gbb + xvb.z;
    ob.w = (pvb.w - st.x)*wb + gbb + xvb.w;
    ((float4*)out)[ia] = oa;
    ((float4*)out)[ib] = ob;
}

// ======================= launch =============================================
extern "C" void kernel_launch(void* const* d_in, const int* in_sizes, int n_in,
                              void* d_out, int out_size)
{
    const float* x    = (const float*)d_in[0];
    const float* Wq   = (const float*)d_in[1];
    const float* bq   = (const float*)d_in[2];
    const float* Wk   = (const float*)d_in[3];
    const float* bk   = (const float*)d_in[4];
    const float* Wv   = (const float*)d_in[5];
    const float* bv   = (const float*)d_in[6];
    const float* Wo   = (const float*)d_in[7];
    const float* bo   = (const float*)d_in[8];
    const float* gn_w = (const float*)d_in[9];
    const float* gn_b = (const float*)d_in[10];
    float* out = (float*)d_out;

    wcvt_kernel<<<128, 256>>>(Wq, Wk, Wv, Wo);
    qkv_mma_kernel<<<dim3(NB*64, 3), 128>>>(x, bq, bk, bv);
    attn_mma_kernel<<<dim3(NB*NHD, NN/128), 128>>>();
    oproj_mma_kernel<<<NB*64, 128>>>(bo);
    gnapply_kernel<<<NB*NC*NN/4/512, 256>>>(x, gn_w, gn_b, out);
}